// round 9
// baseline (speedup 1.0000x reference)
#include <cuda_runtime.h>

// Problem constants (fixed by the dataset)
#define B_   128
#define D_   512
#define KP_  2048        // K + num_positive
#define NF_  16084
#define NP_  604731
#define INV_T 14.2857142857142857f   // 1 / 0.07

// ---- grid layout ----
#define LOSS1_BLKS (B_ * 4)          // 512: mem1 loss, 4 chunks of 512 rows per b
#define COPY1_BLKS 52
#define BANK2_BLKS 1996
#define RPB 303                      // rows of mem2 per bank2 block (1996*303 >= NP)
#define TOTAL_BLKS (LOSS1_BLKS + COPY1_BLKS + BANK2_BLKS)   // 2560

#define CAP 16                       // max references tracked per mem2 row

// ---- deterministic scratch (no float atomics anywhere) ----
__device__ int   g_cnt[NP_];                 // per-row reference count
__device__ int   g_slot[(size_t)NP_ * CAP];  // packed (b<<11 | k)
__device__ float g_lg2[2][B_][KP_];          // bank2 logits (every slot written)
__device__ float g_m1[B_][4], g_s1[B_][4];   // bank1 partials, t=0
__device__ float g_m2[B_][4], g_s2[B_][4];   // bank1 partials, t=1
__device__ float g_pos1[B_][2];              // bank1 k=0 logits (t0,t1)
__device__ float g_m2r[2][B_], g_s2r[2][B_]; // bank2 reduced (max, sumexp)

// ---------------------------------------------------------------------------
// Prep: zero the per-row counters (needed every graph replay).
// ---------------------------------------------------------------------------
__global__ void zero_kernel()
{
    const int i = blockIdx.x * blockDim.x + threadIdx.x;
    if (i < NP_) g_cnt[i] = 0;
}

// Prep: build inverted index row -> (b,k). Order within a bucket is
// nondeterministic but irrelevant: every (b,k) owns its own output slot.
__global__ void build_kernel(const int* __restrict__ idx2)
{
    const int t = blockIdx.x * blockDim.x + threadIdx.x;
    if (t >= B_ * KP_) return;
    const int b = t >> 11;          // / KP_
    const int k = t & (KP_ - 1);
    const int r = __ldg(idx2 + t);
    const int pos = atomicAdd(&g_cnt[r], 1);
    if (pos < CAP) g_slot[(size_t)r * CAP + pos] = (b << 11) | k;
}

// ---------------------------------------------------------------------------
// Bank1 copy span: dst = out+1 is 4B off 16B alignment. Vectorize on dst
// (thread covers 4 consecutive dst floats at j ≡ 3 mod 4 -> STG.128);
// loads scalar but aggregate-coalesced; 4x unroll for MLP. Cached reads
// (bank1 = 32MB, warms L2 for the mem1 loss gathers); streaming stores.
// ---------------------------------------------------------------------------
__device__ __forceinline__ void copy_span1(const float* __restrict__ src,
                                           float* __restrict__ dst,
                                           long long n,
                                           long long tid0, long long stride)
{
    const long long PRO = 3;
    const long long nv = (n - PRO) >> 2;

    if (tid0 < PRO) dst[tid0] = src[tid0];

    long long v = tid0;
    for (; v + 3 * stride < nv; v += 4 * stride) {
        const long long j0 = PRO + 4 * v;
        const long long j1 = PRO + 4 * (v + stride);
        const long long j2 = PRO + 4 * (v + 2 * stride);
        const long long j3 = PRO + 4 * (v + 3 * stride);
        float4 r0, r1, r2, r3;
        r0.x = src[j0+0]; r0.y = src[j0+1]; r0.z = src[j0+2]; r0.w = src[j0+3];
        r1.x = src[j1+0]; r1.y = src[j1+1]; r1.z = src[j1+2]; r1.w = src[j1+3];
        r2.x = src[j2+0]; r2.y = src[j2+1]; r2.z = src[j2+2]; r2.w = src[j2+3];
        r3.x = src[j3+0]; r3.y = src[j3+1]; r3.z = src[j3+2]; r3.w = src[j3+3];
        __stcs((float4*)(dst + j0), r0);
        __stcs((float4*)(dst + j1), r1);
        __stcs((float4*)(dst + j2), r2);
        __stcs((float4*)(dst + j3), r3);
    }
    for (; v < nv; v += stride) {
        const long long j = PRO + 4 * v;
        float4 r;
        r.x = src[j+0]; r.y = src[j+1]; r.z = src[j+2]; r.w = src[j+3];
        __stcs((float4*)(dst + j), r);
    }

    const long long tail = PRO + 4 * nv;
    const long long t = tail + tid0;
    if (t < n) dst[t] = src[t];
}

// ---------------------------------------------------------------------------
// Fused kernel. Role by block id (interleaved so every wave mixes work):
//   blk % 5 == 2 (first 512 such) -> bank1 loss block
//   else: cid = blk - #loss_before; cid < 52 -> bank1 copy;
//         else bank2 copy+dot block over rows [c2*RPB, ...).
//
// Bank2 block: warp-per-row. Warp loads the 2KB row into registers (lane
// holds 16 consecutive floats), stores it realigned to out (3 shuffles +
// 4 STG.128 + 4 scalar edges per row), then for each inverted-index entry
// computes dot(row, v1[b]) and dot(row, v2[b]) from the SAME registers
// (zero extra row traffic), writing g_lg2[t][b][k].
// ---------------------------------------------------------------------------
__global__ void __launch_bounds__(512) fused_kernel(const float* __restrict__ v1,
                                                    const float* __restrict__ v2,
                                                    const int*   __restrict__ idx1,
                                                    const float* __restrict__ mem1,
                                                    const float* __restrict__ mem2,
                                                    float* __restrict__ out)
{
    const int blk = blockIdx.x;
    const bool is_loss = (blk % 5 == 2) && (blk / 5 < 512);
    const int tid  = threadIdx.x;
    const int warp = tid >> 5;
    const int lane = tid & 31;

    if (!is_loss) {
        int nl = (blk + 2) / 5; if (nl > 512) nl = 512;
        const int cid = blk - nl;                 // 0..2047
        const long long N1 = (long long)NF_ * D_;

        if (cid < COPY1_BLKS) {
            const long long stride = (long long)COPY1_BLKS * 512;
            const long long tid0 = (long long)cid * 512 + tid;
            copy_span1(mem1, out + 1, N1, tid0, stride);
            return;
        }

        // -------- bank2: copy + inverted-gather dot --------
        const int c2 = cid - COPY1_BLKS;          // 0..1995
        const int r_begin = c2 * RPB;
        int r_end = r_begin + RPB; if (r_end > NP_) r_end = NP_;
        float* __restrict__ dstb = out + 1 + N1;

        for (int r = r_begin + warp; r < r_end; r += 16) {
            const float* __restrict__ src = mem2 + (size_t)r * D_;
            float4 a[4];
#pragma unroll
            for (int i = 0; i < 4; i++)
                a[i] = ((const float4*)src)[lane * 4 + i];

            // ---- realigned store (dst element offset ≡ 1 mod 4) ----
            float* __restrict__ drow = dstb + (size_t)r * D_;
            if (lane == 0) { drow[0] = a[0].x; drow[1] = a[0].y; drow[2] = a[0].z; }
            if (lane == 31) drow[511] = a[3].w;
            const float nx = __shfl_down_sync(0xffffffffu, a[0].x, 1);
            const float ny = __shfl_down_sync(0xffffffffu, a[0].y, 1);
            const float nz = __shfl_down_sync(0xffffffffu, a[0].z, 1);
            float4 s0 = {a[0].w, a[1].x, a[1].y, a[1].z};
            float4 s1v = {a[1].w, a[2].x, a[2].y, a[2].z};
            float4 s2v = {a[2].w, a[3].x, a[3].y, a[3].z};
            __stcs((float4*)(drow + 16 * lane + 3),  s0);
            __stcs((float4*)(drow + 16 * lane + 7),  s1v);
            __stcs((float4*)(drow + 16 * lane + 11), s2v);
            if (lane < 31) {
                float4 s3 = {a[3].w, nx, ny, nz};
                __stcs((float4*)(drow + 16 * lane + 15), s3);
            }

            // ---- references to this row: compute logits from registers ----
            int cnt = g_cnt[r]; if (cnt > CAP) cnt = CAP;
            for (int e = 0; e < cnt; e++) {
                const int ent = g_slot[(size_t)r * CAP + e];
                const int b = ent >> 11, k = ent & (KP_ - 1);
                const float4* __restrict__ x1p =
                    (const float4*)(v1 + (size_t)b * D_) + lane * 4;
                const float4* __restrict__ x2p =
                    (const float4*)(v2 + (size_t)b * D_) + lane * 4;
                float d1 = 0.0f, d2 = 0.0f;
#pragma unroll
                for (int i = 0; i < 4; i++) {
                    float4 x1 = x1p[i], x2 = x2p[i];
                    d1 += a[i].x*x1.x + a[i].y*x1.y + a[i].z*x1.z + a[i].w*x1.w;
                    d2 += a[i].x*x2.x + a[i].y*x2.y + a[i].z*x2.z + a[i].w*x2.w;
                }
#pragma unroll
                for (int off = 16; off; off >>= 1) {
                    d1 += __shfl_xor_sync(0xffffffffu, d1, off);
                    d2 += __shfl_xor_sync(0xffffffffu, d2, off);
                }
                if (lane == 0) {
                    g_lg2[0][b][k] = d1 * INV_T;
                    g_lg2[1][b][k] = d2 * INV_T;
                }
            }
        }
        return;
    }

    // -------- bank1 loss partial: (b, chunk of 512 rows) --------
    const int l     = blk / 5;       // 0..511
    const int b     = l >> 2;
    const int chunk = l & 3;
    const int NW    = 16;

    __shared__ float sm_m1[NW], sm_s1[NW], sm_m2[NW], sm_s2[NW];

    float4 rv1[4], rv2[4];
#pragma unroll
    for (int c = 0; c < 4; c++) {
        rv1[c] = *(const float4*)(v1 + (size_t)b * D_ + 128 * c + 4 * lane);
        rv2[c] = *(const float4*)(v2 + (size_t)b * D_ + 128 * c + 4 * lane);
    }

    const int* __restrict__ idx = idx1 + b * KP_ + chunk * 512;

    float m1 = -1e30f, s1 = 0.0f;
    float m2 = -1e30f, s2 = 0.0f;

#pragma unroll 1
    for (int r = 2 * warp; r < 512; r += 2 * NW) {
        const float* __restrict__ rowA = mem1 + (size_t)__ldg(idx + r)     * D_;
        const float* __restrict__ rowB = mem1 + (size_t)__ldg(idx + r + 1) * D_;

        float a1 = 0.0f, a2 = 0.0f, c1 = 0.0f, c2 = 0.0f;
#pragma unroll
        for (int c = 0; c < 4; c++) {
            float4 wa = *(const float4*)(rowA + 128 * c + 4 * lane);
            float4 wb = *(const float4*)(rowB + 128 * c + 4 * lane);
            a1 += wa.x * rv1[c].x + wa.y * rv1[c].y + wa.z * rv1[c].z + wa.w * rv1[c].w;
            a2 += wa.x * rv2[c].x + wa.y * rv2[c].y + wa.z * rv2[c].z + wa.w * rv2[c].w;
            c1 += wb.x * rv1[c].x + wb.y * rv1[c].y + wb.z * rv1[c].z + wb.w * rv1[c].w;
            c2 += wb.x * rv2[c].x + wb.y * rv2[c].y + wb.z * rv2[c].z + wb.w * rv2[c].w;
        }
#pragma unroll
        for (int off = 16; off; off >>= 1) {
            a1 += __shfl_xor_sync(0xffffffffu, a1, off);
            a2 += __shfl_xor_sync(0xffffffffu, a2, off);
            c1 += __shfl_xor_sync(0xffffffffu, c1, off);
            c2 += __shfl_xor_sync(0xffffffffu, c2, off);
        }
        a1 *= INV_T; a2 *= INV_T; c1 *= INV_T; c2 *= INV_T;

        if (lane == 0 && r == 0 && chunk == 0) {
            g_pos1[b][0] = a1;
            g_pos1[b][1] = a2;
        }

        float nm = fmaxf(m1, fmaxf(a1, c1));
        s1 = s1 * __expf(m1 - nm) + __expf(a1 - nm) + __expf(c1 - nm);
        m1 = nm;
        nm = fmaxf(m2, fmaxf(a2, c2));
        s2 = s2 * __expf(m2 - nm) + __expf(a2 - nm) + __expf(c2 - nm);
        m2 = nm;
    }

    if (lane == 0) {
        sm_m1[warp] = m1; sm_s1[warp] = s1;
        sm_m2[warp] = m2; sm_s2[warp] = s2;
    }
    __syncthreads();

    if (tid == 0) {
        float M1 = -1e30f, M2 = -1e30f;
#pragma unroll
        for (int w = 0; w < NW; w++) {
            M1 = fmaxf(M1, sm_m1[w]);
            M2 = fmaxf(M2, sm_m2[w]);
        }
        float S1 = 0.0f, S2 = 0.0f;
#pragma unroll
        for (int w = 0; w < NW; w++) {
            S1 += sm_s1[w] * expf(sm_m1[w] - M1);
            S2 += sm_s2[w] * expf(sm_m2[w] - M2);
        }
        g_m1[b][chunk] = M1; g_s1[b][chunk] = S1;
        g_m2[b][chunk] = M2; g_s2[b][chunk] = S2;
    }
}

// ---------------------------------------------------------------------------
// Kernel: momentum row updates (blocks 0..255) + bank2 softmax reduce
// (blocks 256..511). Duplicate labels: scatter "last update wins".
// ---------------------------------------------------------------------------
__global__ void __launch_bounds__(128) update_kernel(const float* __restrict__ v1,
                                                     const int*   __restrict__ y1,
                                                     const float* __restrict__ v2,
                                                     const int*   __restrict__ y2,
                                                     const float* __restrict__ mem1,
                                                     const float* __restrict__ mem2,
                                                     float* __restrict__ out)
{
    const int blk = blockIdx.x;
    const int tid = threadIdx.x;

    if (blk >= 2 * B_) {
        // ---- bank2 reduce: (t, b) -> max + sumexp over KP logits ----
        const int q = blk - 2 * B_;          // 0..255
        const int t = q >> 7, b = q & 127;
        const float* __restrict__ lg = &g_lg2[t][b][0];

        __shared__ float red[128];

        float m = -1e30f;
#pragma unroll
        for (int j = 0; j < KP_ / 128; j++)
            m = fmaxf(m, lg[tid + 128 * j]);
        red[tid] = m;
        __syncthreads();
#pragma unroll
        for (int s = 64; s; s >>= 1) {
            if (tid < s) red[tid] = fmaxf(red[tid], red[tid + s]);
            __syncthreads();
        }
        const float M = red[0];
        __syncthreads();

        float s = 0.0f;
#pragma unroll
        for (int j = 0; j < KP_ / 128; j++)
            s += expf(lg[tid + 128 * j] - M);
        red[tid] = s;
        __syncthreads();
#pragma unroll
        for (int sh = 64; sh; sh >>= 1) {
            if (tid < sh) red[tid] += red[tid + sh];
            __syncthreads();
        }
        if (tid == 0) { g_m2r[t][b] = M; g_s2r[t][b] = red[0]; }
        return;
    }

    // ---- momentum row update ----
    const int bank = blk / B_;   // 0 -> mem1, 1 -> mem2
    const int b    = blk % B_;

    const int*   __restrict__ y   = bank ? y2 : y1;
    const float* __restrict__ v   = bank ? v2 : v1;
    const float* __restrict__ mem = bank ? mem2 : mem1;
    float* __restrict__ dst = out + 1 + (bank ? (size_t)NF_ * D_ : (size_t)0);

    const int row = __ldg(y + b);
    for (int b2 = b + 1; b2 < B_; b2++)
        if (__ldg(y + b2) == row) return;   // last occurrence wins

    float p[4];
    float ss = 0.0f;
#pragma unroll
    for (int j = 0; j < 4; j++) {
        int d = tid + j * 128;
        float x = 0.5f * __ldg(mem + (size_t)row * D_ + d)
                + 0.5f * __ldg(v + (size_t)b * D_ + d);
        p[j] = x;
        ss += x * x;
    }
#pragma unroll
    for (int off = 16; off; off >>= 1)
        ss += __shfl_xor_sync(0xffffffffu, ss, off);

    __shared__ float wsum[4];
    if ((tid & 31) == 0) wsum[tid >> 5] = ss;
    __syncthreads();
    float tot = wsum[0] + wsum[1] + wsum[2] + wsum[3];
    float inv = 1.0f / sqrtf(tot);

#pragma unroll
    for (int j = 0; j < 4; j++) {
        int d = tid + j * 128;
        dst[(size_t)row * D_ + d] = p[j] * inv;
    }
}

// ---------------------------------------------------------------------------
// Finalize: merge bank1 chunk partials with bank2 reduced partials per
// (t,b), assemble the loss. Deterministic tree sum.
// ---------------------------------------------------------------------------
__global__ void __launch_bounds__(128) finalize_kernel(float* __restrict__ out)
{
    const int b = threadIdx.x;   // 128 threads, one per batch element

    // t = 0
    float M0 = g_m2r[0][b];
#pragma unroll
    for (int c = 0; c < 4; c++) M0 = fmaxf(M0, g_m1[b][c]);
    float S0 = g_s2r[0][b] * expf(g_m2r[0][b] - M0);
#pragma unroll
    for (int c = 0; c < 4; c++) S0 += g_s1[b][c] * expf(g_m1[b][c] - M0);
    const float lse0 = M0 + logf(S0);

    // t = 1
    float M1 = g_m2r[1][b];
#pragma unroll
    for (int c = 0; c < 4; c++) M1 = fmaxf(M1, g_m2[b][c]);
    float S1 = g_s2r[1][b] * expf(g_m2r[1][b] - M1);
#pragma unroll
    for (int c = 0; c < 4; c++) S1 += g_s2[b][c] * expf(g_m2[b][c] - M1);
    const float lse1 = M1 + logf(S1);

    float contrib = 0.5f * (g_pos1[b][0] + g_lg2[0][b][0]) - lse0
                  + 0.5f * (g_pos1[b][1] + g_lg2[1][b][0]) - lse1;

    __shared__ float red[128];
    red[b] = contrib;
    __syncthreads();
#pragma unroll
    for (int s = 64; s; s >>= 1) {
        if (b < s) red[b] += red[b + s];
        __syncthreads();
    }
    if (b == 0) out[0] = -red[0] / (2.0f * B_);
}

// ---------------------------------------------------------------------------
// Launch
// inputs: 0 v1(f32 B*D) 1 y1(i32 B) 2 v2 3 y2 4 idx1(i32 B*KP) 5 idx2
//         6 memory_v1(f32 NF*D) 7 memory_v2(f32 NP*D)
// output: [loss, new_mem_v1 (NF*D), new_mem_v2 (NP*D)]
// ---------------------------------------------------------------------------
extern "C" void kernel_launch(void* const* d_in, const int* in_sizes, int n_in,
                              void* d_out, int out_size)
{
    (void)in_sizes; (void)n_in; (void)out_size;
    const float* v1   = (const float*)d_in[0];
    const int*   y1   = (const int*)  d_in[1];
    const float* v2   = (const float*)d_in[2];
    const int*   y2   = (const int*)  d_in[3];
    const int*   idx1 = (const int*)  d_in[4];
    const int*   idx2 = (const int*)  d_in[5];
    const float* mem1 = (const float*)d_in[6];
    const float* mem2 = (const float*)d_in[7];
    float* out = (float*)d_out;

    zero_kernel<<<(NP_ + 1023) / 1024, 1024>>>();
    build_kernel<<<(B_ * KP_) / 512, 512>>>(idx2);
    fused_kernel<<<TOTAL_BLKS, 512>>>(v1, v2, idx1, mem1, mem2, out);
    update_kernel<<<4 * B_, 128>>>(v1, y1, v2, y2, mem1, mem2, out);
    finalize_kernel<<<1, 128>>>(out);
}

// round 10
// speedup vs baseline: 1.0736x; 1.0736x over previous
#include <cuda_runtime.h>

// Problem constants (fixed by the dataset)
#define B_   128
#define D_   512
#define KP_  2048        // K + num_positive
#define NF_  16084
#define NP_  604731
#define INV_T 14.2857142857142857f   // 1 / 0.07

#define NCHUNK 8                      // loss chunks per batch element
#define ROWS_PER_CHUNK (2 * KP_ / NCHUNK)   // 512 rows per chunk

#define COPY_BLKS_1 52
#define COPY_BLKS_2 1996
#define COPY_BLKS   (COPY_BLKS_1 + COPY_BLKS_2)   // 2048
#define LOSS_BLKS   (B_ * NCHUNK)                 // 1024
#define TOTAL_BLKS  (COPY_BLKS + LOSS_BLKS)       // 3072

// Deterministic scratch (no float atomics anywhere)
__device__ float g_m1[B_][NCHUNK], g_s1[B_][NCHUNK];
__device__ float g_m2[B_][NCHUNK], g_s2[B_][NCHUNK];
__device__ float g_pos[B_][4];   // logits at k=0 (t0,t1) and k=KP (t0,t1)

// ---------------------------------------------------------------------------
// Copy span: dst is 4B off 16B alignment (dst = out+1+..., offsets mult of 4).
// Vectorize on the destination: thread covers 4 consecutive dst floats
// starting at j ≡ 3 (mod 4) -> STG.128; the 4 loads per chunk are scalar but
// aggregate-coalesced. 8x grid-stride unroll: 32 loads (128 B) in flight per
// thread -> DRAM latency covered even when copy shares SMs with loss blocks.
// SRC_CACHE: 0=streaming (.cs), 1=cached (warm L2 for mem1 gathers).
// Destination stores always streaming (pure write-once traffic).
// ---------------------------------------------------------------------------
template<int SRC_CACHE>
__device__ __forceinline__ void copy_span(const float* __restrict__ src,
                                          float* __restrict__ dst,
                                          long long n,
                                          long long tid0, long long stride)
{
    const long long PRO = 3;
    const long long nv = (n - PRO) >> 2;

    if (tid0 < PRO) dst[tid0] = src[tid0];

#define LD1(J,OFS) (SRC_CACHE ? src[(J)+(OFS)] : __ldcs(src + (J) + (OFS)))

    long long v = tid0;
    for (; v + 7 * stride < nv; v += 8 * stride) {
        long long j[8];
        float4 r[8];
#pragma unroll
        for (int u = 0; u < 8; u++) j[u] = PRO + 4 * (v + u * stride);
#pragma unroll
        for (int u = 0; u < 8; u++) {
            r[u].x = LD1(j[u],0); r[u].y = LD1(j[u],1);
            r[u].z = LD1(j[u],2); r[u].w = LD1(j[u],3);
        }
#pragma unroll
        for (int u = 0; u < 8; u++)
            __stcs((float4*)(dst + j[u]), r[u]);
    }
    for (; v + 3 * stride < nv; v += 4 * stride) {
        long long j[4];
        float4 r[4];
#pragma unroll
        for (int u = 0; u < 4; u++) j[u] = PRO + 4 * (v + u * stride);
#pragma unroll
        for (int u = 0; u < 4; u++) {
            r[u].x = LD1(j[u],0); r[u].y = LD1(j[u],1);
            r[u].z = LD1(j[u],2); r[u].w = LD1(j[u],3);
        }
#pragma unroll
        for (int u = 0; u < 4; u++)
            __stcs((float4*)(dst + j[u]), r[u]);
    }
    for (; v < nv; v += stride) {
        const long long j = PRO + 4 * v;
        float4 r;
        r.x = LD1(j,0); r.y = LD1(j,1); r.z = LD1(j,2); r.w = LD1(j,3);
        __stcs((float4*)(dst + j), r);
    }
#undef LD1

    const long long tail = PRO + 4 * nv;
    const long long t = tail + tid0;
    if (t < n) dst[t] = src[t];
}

// row load: STREAMROW=1 -> evict-first (random one-time mem2 gathers:
// don't let 437MB of gather traffic thrash L2 / evict the resident mem1).
template<int STREAMROW>
__device__ __forceinline__ float4 ld_row(const float* p)
{
    if (STREAMROW) return __ldcs((const float4*)p);
    return *(const float4*)p;
}

// ---------------------------------------------------------------------------
// Loss chunk body (templated on bank residency).
// 16 warps; warp w handles rows r = 2*w + 32*i (+1) of the chunk's 512 rows.
// Lanes keep v1[b]/v2[b] in registers; per iteration 8 independent LDG.128 +
// 64 FFMA + 4 interleaved butterfly chains, then online-softmax updates.
// ---------------------------------------------------------------------------
template<int STREAMROW>
__device__ __forceinline__ void loss_chunk(const float* __restrict__ mem,
                                           const int*   __restrict__ idx,
                                           const float4 rv1[4], const float4 rv2[4],
                                           int warp, int lane,
                                           float& m1, float& s1,
                                           float& m2, float& s2,
                                           int b, int chunk)
{
    const int NW = 16;
#pragma unroll 1
    for (int r = 2 * warp; r < ROWS_PER_CHUNK; r += 2 * NW) {
        const float* __restrict__ rowA = mem + (size_t)__ldg(idx + r)     * D_;
        const float* __restrict__ rowB = mem + (size_t)__ldg(idx + r + 1) * D_;

        float a1 = 0.0f, a2 = 0.0f, c1 = 0.0f, c2 = 0.0f;
#pragma unroll
        for (int c = 0; c < 4; c++) {
            float4 wa = ld_row<STREAMROW>(rowA + 128 * c + 4 * lane);
            float4 wb = ld_row<STREAMROW>(rowB + 128 * c + 4 * lane);
            a1 += wa.x * rv1[c].x + wa.y * rv1[c].y + wa.z * rv1[c].z + wa.w * rv1[c].w;
            a2 += wa.x * rv2[c].x + wa.y * rv2[c].y + wa.z * rv2[c].z + wa.w * rv2[c].w;
            c1 += wb.x * rv1[c].x + wb.y * rv1[c].y + wb.z * rv1[c].z + wb.w * rv1[c].w;
            c2 += wb.x * rv2[c].x + wb.y * rv2[c].y + wb.z * rv2[c].z + wb.w * rv2[c].w;
        }
#pragma unroll
        for (int off = 16; off; off >>= 1) {
            a1 += __shfl_xor_sync(0xffffffffu, a1, off);
            a2 += __shfl_xor_sync(0xffffffffu, a2, off);
            c1 += __shfl_xor_sync(0xffffffffu, c1, off);
            c2 += __shfl_xor_sync(0xffffffffu, c2, off);
        }
        a1 *= INV_T; a2 *= INV_T; c1 *= INV_T; c2 *= INV_T;

        // positive logits: global k==0 -> chunk0,r==0; k==KP -> chunk4,r==0
        if (lane == 0 && r == 0 && (chunk == 0 || chunk == NCHUNK / 2)) {
            const int o = (chunk == 0) ? 0 : 2;
            g_pos[b][o + 0] = a1;
            g_pos[b][o + 1] = a2;
        }

        float nm = fmaxf(m1, fmaxf(a1, c1));
        s1 = s1 * __expf(m1 - nm) + __expf(a1 - nm) + __expf(c1 - nm);
        m1 = nm;
        nm = fmaxf(m2, fmaxf(a2, c2));
        s2 = s2 * __expf(m2 - nm) + __expf(a2 - nm) + __expf(c2 - nm);
        m2 = nm;
    }
}

// ---------------------------------------------------------------------------
// Fused kernel. Roles INTERLEAVED by block id so every scheduling wave
// carries ~2/3 copy + 1/3 loss work (true overlap at 1 block/SM):
//   blk % 3 == 1 -> loss block, loss_id = blk / 3          (1024 blocks)
//   otherwise    -> copy block, copy_id = blk - (blk+2)/3  (2048 blocks)
// ---------------------------------------------------------------------------
__global__ void __launch_bounds__(512) fused_kernel(const float* __restrict__ v1,
                                                    const float* __restrict__ v2,
                                                    const int*   __restrict__ idx1,
                                                    const int*   __restrict__ idx2,
                                                    const float* __restrict__ mem1,
                                                    const float* __restrict__ mem2,
                                                    float* __restrict__ out)
{
    const int blk = blockIdx.x;
    const bool is_loss = (blk % 3 == 1) && (blk / 3 < LOSS_BLKS);

    // ---------------- copy part ----------------
    if (!is_loss) {
        const int cid = blk - (blk + 2) / 3;     // 0..COPY_BLKS-1
        const long long N1 = (long long)NF_ * D_;
        const long long N2 = (long long)NP_ * D_;
        if (cid < COPY_BLKS_1) {
            const long long stride = (long long)COPY_BLKS_1 * 512;
            const long long tid0 = (long long)cid * 512 + threadIdx.x;
            copy_span<1>(mem1, out + 1, N1, tid0, stride);     // cached: warm L2
        } else {
            const long long stride = (long long)COPY_BLKS_2 * 512;
            const long long tid0 = (long long)(cid - COPY_BLKS_1) * 512 + threadIdx.x;
            copy_span<0>(mem2, out + 1 + N1, N2, tid0, stride); // streaming
        }
        return;
    }

    // ---------------- loss partial part ----------------
    const int l     = blk / 3;       // 0..1023
    const int b     = l >> 3;        // / NCHUNK
    const int chunk = l & 7;         // % NCHUNK
    const int tid   = threadIdx.x;
    const int warp  = tid >> 5;
    const int lane  = tid & 31;
    const int NW    = 16;

    __shared__ float sm_m1[NW], sm_s1[NW], sm_m2[NW], sm_s2[NW];

    // v1[b], v2[b] into registers: lane covers d = 128*c + 4*lane + {0..3}
    float4 rv1[4], rv2[4];
#pragma unroll
    for (int c = 0; c < 4; c++) {
        rv1[c] = *(const float4*)(v1 + (size_t)b * D_ + 128 * c + 4 * lane);
        rv2[c] = *(const float4*)(v2 + (size_t)b * D_ + 128 * c + 4 * lane);
    }

    // chunk -> bank and local index base
    const int kbase = chunk * ROWS_PER_CHUNK;          // global k of chunk start
    const bool bank2 = (kbase >= KP_);

    float m1 = -1e30f, s1 = 0.0f;
    float m2 = -1e30f, s2 = 0.0f;

    if (bank2) {
        const int* __restrict__ idx = idx2 + b * KP_ + (kbase - KP_);
        loss_chunk<1>(mem2, idx, rv1, rv2, warp, lane, m1, s1, m2, s2, b, chunk);
    } else {
        const int* __restrict__ idx = idx1 + b * KP_ + kbase;
        loss_chunk<0>(mem1, idx, rv1, rv2, warp, lane, m1, s1, m2, s2, b, chunk);
    }

    if (lane == 0) {
        sm_m1[warp] = m1; sm_s1[warp] = s1;
        sm_m2[warp] = m2; sm_s2[warp] = s2;
    }
    __syncthreads();

    if (tid == 0) {
        float M1 = -1e30f, M2 = -1e30f;
#pragma unroll
        for (int w = 0; w < NW; w++) {
            M1 = fmaxf(M1, sm_m1[w]);
            M2 = fmaxf(M2, sm_m2[w]);
        }
        float S1 = 0.0f, S2 = 0.0f;
#pragma unroll
        for (int w = 0; w < NW; w++) {
            S1 += sm_s1[w] * expf(sm_m1[w] - M1);
            S2 += sm_s2[w] * expf(sm_m2[w] - M2);
        }
        g_m1[b][chunk] = M1; g_s1[b][chunk] = S1;
        g_m2[b][chunk] = M2; g_s2[b][chunk] = S2;
    }
}

// ---------------------------------------------------------------------------
// Kernel 2: momentum row updates (blocks 0..2B-1) + loss finalize (block 2B).
// Duplicate labels: scatter "last update wins".
// ---------------------------------------------------------------------------
__global__ void __launch_bounds__(128) update_kernel(const float* __restrict__ v1,
                                                     const int*   __restrict__ y1,
                                                     const float* __restrict__ v2,
                                                     const int*   __restrict__ y2,
                                                     const float* __restrict__ mem1,
                                                     const float* __restrict__ mem2,
                                                     float* __restrict__ out)
{
    const int blk = blockIdx.x;

    if (blk == 2 * B_) {  // ---- loss finalize: thread b merges chunks ----
        const int tid = threadIdx.x;   // 128 threads, one per b
        float contrib;
        {
            const int b = tid;
            float M1 = -1e30f, M2 = -1e30f;
#pragma unroll
            for (int j = 0; j < NCHUNK; j++) {
                M1 = fmaxf(M1, g_m1[b][j]);
                M2 = fmaxf(M2, g_m2[b][j]);
            }
            float S1 = 0.0f, S2 = 0.0f;
#pragma unroll
            for (int j = 0; j < NCHUNK; j++) {
                S1 += g_s1[b][j] * expf(g_m1[b][j] - M1);
                S2 += g_s2[b][j] * expf(g_m2[b][j] - M2);
            }
            float lse1 = M1 + logf(S1);
            float lse2 = M2 + logf(S2);
            contrib = 0.5f * (g_pos[b][0] + g_pos[b][2]) - lse1
                    + 0.5f * (g_pos[b][1] + g_pos[b][3]) - lse2;
        }
        __shared__ float red[128];
        red[tid] = contrib;
        __syncthreads();
#pragma unroll
        for (int s = 64; s; s >>= 1) {
            if (tid < s) red[tid] += red[tid + s];
            __syncthreads();
        }
        if (tid == 0) out[0] = -red[0] / (2.0f * B_);
        return;
    }

    const int bank = blk / B_;   // 0 -> mem1, 1 -> mem2
    const int b    = blk % B_;

    const int*   __restrict__ y   = bank ? y2 : y1;
    const float* __restrict__ v   = bank ? v2 : v1;
    const float* __restrict__ mem = bank ? mem2 : mem1;
    float* __restrict__ dst = out + 1 + (bank ? (size_t)NF_ * D_ : (size_t)0);

    const int row = __ldg(y + b);
    // last-occurrence-wins: skip if a later b' writes the same row
    for (int b2 = b + 1; b2 < B_; b2++)
        if (__ldg(y + b2) == row) return;   // uniform across block

    const int tid = threadIdx.x;
    float p[4];
    float ss = 0.0f;
#pragma unroll
    for (int j = 0; j < 4; j++) {
        int d = tid + j * 128;
        float x = 0.5f * __ldg(mem + (size_t)row * D_ + d)
                + 0.5f * __ldg(v + (size_t)b * D_ + d);
        p[j] = x;
        ss += x * x;
    }
#pragma unroll
    for (int off = 16; off; off >>= 1)
        ss += __shfl_xor_sync(0xffffffffu, ss, off);

    __shared__ float wsum[4];
    if ((tid & 31) == 0) wsum[tid >> 5] = ss;
    __syncthreads();
    float tot = wsum[0] + wsum[1] + wsum[2] + wsum[3];
    float inv = 1.0f / sqrtf(tot);

#pragma unroll
    for (int j = 0; j < 4; j++) {
        int d = tid + j * 128;
        dst[(size_t)row * D_ + d] = p[j] * inv;
    }
}

// ---------------------------------------------------------------------------
// Launch
// inputs: 0 v1(f32 B*D) 1 y1(i32 B) 2 v2 3 y2 4 idx1(i32 B*KP) 5 idx2
//         6 memory_v1(f32 NF*D) 7 memory_v2(f32 NP*D)
// output: [loss, new_mem_v1 (NF*D), new_mem_v2 (NP*D)]
// ---------------------------------------------------------------------------
extern "C" void kernel_launch(void* const* d_in, const int* in_sizes, int n_in,
                              void* d_out, int out_size)
{
    (void)in_sizes; (void)n_in; (void)out_size;
    const float* v1   = (const float*)d_in[0];
    const int*   y1   = (const int*)  d_in[1];
    const float* v2   = (const float*)d_in[2];
    const int*   y2   = (const int*)  d_in[3];
    const int*   idx1 = (const int*)  d_in[4];
    const int*   idx2 = (const int*)  d_in[5];
    const float* mem1 = (const float*)d_in[6];
    const float* mem2 = (const float*)d_in[7];
    float* out = (float*)d_out;

    fused_kernel<<<TOTAL_BLKS, 512>>>(v1, v2, idx1, idx2, mem1, mem2, out);
    update_kernel<<<2 * B_ + 1, 128>>>(v1, y1, v2, y2, mem1, mem2, out);
}